// round 8
// baseline (speedup 1.0000x reference)
#include <cuda_runtime.h>
#include <cuda_bf16.h>

#define B_ 64
#define T_ 512
#define D_ 256
#define C_ 20
#define NTOK (B_*T_)

// Scratch (static device arrays: allocation-free)
__device__ float g_logits[NTOK*C_];
__device__ float g_probs [NTOK*C_];
__device__ float g_nll   [B_];

// ---------------------------------------------------------------------------
// k1: emb gather + LayerNorm folded into (256->20) linear + log_softmax.
// One thread per token; warp-cooperative smem staging of emb rows.
// ---------------------------------------------------------------------------
__global__ __launch_bounds__(128) void k1_logits(
    const int*   __restrict__ words,
    const float* __restrict__ emb,
    const float* __restrict__ ln_g,
    const float* __restrict__ ln_b,
    const float* __restrict__ W,
    const float* __restrict__ bvec)
{
    __shared__ float sWg[D_*C_];     // ln_g[d]*W[d][c]
    __shared__ float sX[128*33];     // 32-wide chunk of 128 token rows, pad 33
    __shared__ float sCol[C_];       // column sums of Wg
    __shared__ float sBB[C_];        // b[c] + sum_d ln_b[d]*W[d][c]
    __shared__ int   sWid[128];

    const int tid = threadIdx.x;
    const int tok = blockIdx.x * 128 + tid;

    sWid[tid] = words[tok];
    for (int idx = tid; idx < D_*C_; idx += 128) {
        int d = idx / C_;
        sWg[idx] = ln_g[d] * W[idx];
    }
    __syncthreads();

    if (tid < C_) {
        float cs = 0.f, bb = bvec[tid];
        #pragma unroll 8
        for (int d = 0; d < D_; d++) {
            cs += sWg[d*C_ + tid];
            bb += ln_b[d] * W[d*C_ + tid];
        }
        sCol[tid] = cs;
        sBB[tid]  = bb;
    }

    float acc[C_];
    #pragma unroll
    for (int k = 0; k < C_; k++) acc[k] = 0.f;
    float sum = 0.f, sq = 0.f;

    for (int ch = 0; ch < 8; ch++) {
        __syncthreads();   // protect sX from previous iteration's readers
        // cooperative coalesced gather: 128 rows x 32 floats
        #pragma unroll
        for (int k = 0; k < 32; k++) {
            int f = tid + k*128;
            int r = f >> 5, c = f & 31;
            sX[r*33 + c] = emb[sWid[r]*D_ + ch*32 + c];
        }
        __syncthreads();

        const float* xr = &sX[tid*33];
        #pragma unroll
        for (int c = 0; c < 32; c++) {
            float x = xr[c];
            sum += x; sq += x*x;
            const float4* w4 = reinterpret_cast<const float4*>(&sWg[(ch*32 + c)*C_]);
            float4 w0 = w4[0], w1 = w4[1], w2 = w4[2], w3 = w4[3], w4v = w4[4];
            acc[ 0] += x*w0.x;  acc[ 1] += x*w0.y;  acc[ 2] += x*w0.z;  acc[ 3] += x*w0.w;
            acc[ 4] += x*w1.x;  acc[ 5] += x*w1.y;  acc[ 6] += x*w1.z;  acc[ 7] += x*w1.w;
            acc[ 8] += x*w2.x;  acc[ 9] += x*w2.y;  acc[10] += x*w2.z;  acc[11] += x*w2.w;
            acc[12] += x*w3.x;  acc[13] += x*w3.y;  acc[14] += x*w3.z;  acc[15] += x*w3.w;
            acc[16] += x*w4v.x; acc[17] += x*w4v.y; acc[18] += x*w4v.z; acc[19] += x*w4v.w;
        }
    }

    // LayerNorm epilogue + feats
    float mu   = sum * (1.0f / D_);
    float var  = fmaxf(sq * (1.0f / D_) - mu*mu, 0.f);
    float rstd = rsqrtf(var + 1e-5f);

    float f[C_];
    float m = -3.402823e38f;
    #pragma unroll
    for (int c = 0; c < C_; c++) {
        f[c] = rstd * (acc[c] - mu * sCol[c]) + sBB[c];
        m = fmaxf(m, f[c]);
    }
    // log_softmax + probs
    float e[C_];
    float S = 0.f;
    #pragma unroll
    for (int c = 0; c < C_; c++) { e[c] = __expf(f[c] - m); S += e[c]; }
    float L  = logf(S);
    float rS = 1.0f / S;

    float4* lp = reinterpret_cast<float4*>(&g_logits[tok*C_]);
    float4* pp = reinterpret_cast<float4*>(&g_probs [tok*C_]);
    #pragma unroll
    for (int q = 0; q < 5; q++) {
        float4 lv, pv;
        lv.x = f[4*q+0]-m-L; lv.y = f[4*q+1]-m-L; lv.z = f[4*q+2]-m-L; lv.w = f[4*q+3]-m-L;
        pv.x = e[4*q+0]*rS;  pv.y = e[4*q+1]*rS;  pv.z = e[4*q+2]*rS;  pv.w = e[4*q+3]*rS;
        lp[q] = lv;
        pp[q] = pv;
    }
}

// ---------------------------------------------------------------------------
// k2: CRF forward scan (probability domain) + gold score. One block per batch.
//   warp 0: sequential scan  P_j <- prob_j(t) * sum_i P_i * exp(trans)_ij
//           with running log-offset K, butterfly-max renorm every 8 steps.
//   warp 1: gold path score (parallel over t).
// ---------------------------------------------------------------------------
__global__ __launch_bounds__(64) void k2_crf(
    const int*   __restrict__ seq_len,
    const int*   __restrict__ target,
    const float* __restrict__ trans,
    const float* __restrict__ startv,
    const float* __restrict__ endv)
{
    __shared__ float sP[T_*C_];   // this batch's softmax probs (40 KB)
    __shared__ float sE[C_*C_];   // exp(trans)
    __shared__ float sRes[2];     // [0]=normalizer  [1]=gold

    const int b   = blockIdx.x;
    const int tid = threadIdx.x;
    const int len = seq_len[b];

    // stage probs (L2-hot, fully coalesced float4 bulk copy)
    {
        const float4* src = reinterpret_cast<const float4*>(&g_probs[b*T_*C_]);
        float4*       dst = reinterpret_cast<float4*>(sP);
        #pragma unroll 4
        for (int i = tid; i < (T_*C_)/4; i += 64) dst[i] = src[i];
    }
    for (int i = tid; i < C_*C_; i += 64) sE[i] = expf(trans[i]);
    __syncthreads();

    const int warp = tid >> 5;
    const int lane = tid & 31;

    if (warp == 0) {
        const int  j   = lane;
        const bool act = (j < C_);
        float e[C_];
        #pragma unroll
        for (int i = 0; i < C_; i++) e[i] = act ? sE[i*C_ + j] : 0.f;

        float P = act ? sP[j] * expf(startv[j]) : 0.f;
        float K = 0.f;
        // initial renorm (P0 can be ~1e-7 scale)
        {
            float mx = P;
            #pragma unroll
            for (int o = 16; o > 0; o >>= 1) mx = fmaxf(mx, __shfl_xor_sync(0xffffffffu, mx, o));
            K += logf(mx);
            P = P / mx;
        }

        for (int t = 1; t < T_; t++) {
            float pr = act ? sP[t*C_ + j] : 0.f;
            float s0 = 0.f, s1 = 0.f, s2 = 0.f, s3 = 0.f;
            #pragma unroll
            for (int i = 0; i < C_; i += 4) {
                s0 += __shfl_sync(0xffffffffu, P, i    ) * e[i    ];
                s1 += __shfl_sync(0xffffffffu, P, i + 1) * e[i + 1];
                s2 += __shfl_sync(0xffffffffu, P, i + 2) * e[i + 2];
                s3 += __shfl_sync(0xffffffffu, P, i + 3) * e[i + 3];
            }
            float Pn = pr * ((s0 + s1) + (s2 + s3));
            P = (t < len) ? Pn : P;     // per-batch mask: keep alpha when past seq end

            if ((t & 7) == 7) {
                float mx = P;
                #pragma unroll
                for (int o = 16; o > 0; o >>= 1) mx = fmaxf(mx, __shfl_xor_sync(0xffffffffu, mx, o));
                K += logf(mx);
                P = P / mx;
            }
        }
        // normalizer = K + log(sum_j P_j * exp(end_j))
        float v = act ? P * expf(endv[j]) : 0.f;
        #pragma unroll
        for (int o = 16; o > 0; o >>= 1) v += __shfl_xor_sync(0xffffffffu, v, o);
        if (lane == 0) sRes[0] = K + logf(v);
    } else {
        // gold path score (parallel over time)
        const int* tg = &target[b*T_];
        float gs = 0.f;
        for (int t = lane; t < T_; t += 32) {
            if (t < len) {
                int c = tg[t];
                gs += g_logits[(b*T_ + t)*C_ + c];
                if (t >= 1) gs += trans[tg[t-1]*C_ + c];
            }
        }
        #pragma unroll
        for (int o = 16; o > 0; o >>= 1) gs += __shfl_xor_sync(0xffffffffu, gs, o);
        if (lane == 0) {
            gs += startv[tg[0]] + endv[tg[len-1]];
            sRes[1] = gs;
        }
    }
    __syncthreads();
    if (tid == 0) g_nll[b] = sRes[0] - sRes[1];
}

// ---------------------------------------------------------------------------
// k3: mean over 64 batches -> scalar output
// ---------------------------------------------------------------------------
__global__ void k3_mean(float* __restrict__ out)
{
    int lane = threadIdx.x;
    float v = g_nll[lane] + g_nll[lane + 32];
    #pragma unroll
    for (int o = 16; o > 0; o >>= 1) v += __shfl_xor_sync(0xffffffffu, v, o);
    if (lane == 0) out[0] = v * (1.0f / B_);
}

// ---------------------------------------------------------------------------
extern "C" void kernel_launch(void* const* d_in, const int* in_sizes, int n_in,
                              void* d_out, int out_size)
{
    const int*   words   = (const int*)  d_in[0];
    const int*   seq_len = (const int*)  d_in[1];
    const int*   target  = (const int*)  d_in[2];
    const float* emb     = (const float*)d_in[3];
    const float* ln_g    = (const float*)d_in[4];
    const float* ln_b    = (const float*)d_in[5];
    const float* W       = (const float*)d_in[6];
    const float* bvec    = (const float*)d_in[7];
    const float* trans   = (const float*)d_in[8];
    const float* startv  = (const float*)d_in[9];
    const float* endv    = (const float*)d_in[10];

    k1_logits<<<NTOK/128, 128>>>(words, emb, ln_g, ln_b, W, bvec);
    k2_crf   <<<B_, 64>>>(seq_len, target, trans, startv, endv);
    k3_mean  <<<1, 32>>>((float*)d_out);
}

// round 10
// speedup vs baseline: 1.2479x; 1.2479x over previous
#include <cuda_runtime.h>
#include <cuda_bf16.h>
#include <cstdint>

#define B_ 64
#define T_ 512
#define D_ 256
#define C_ 20
#define NTOK (B_*T_)

// padded per-part Wg segment: 64 d * 20 c = 1280 + 8 pad = 1288 words
#define SEG_ 1288
#define WGP_ (4*SEG_)

// Scratch (static device arrays: allocation-free)
__device__ float g_logits[NTOK*C_];
__device__ float g_probs [NTOK*C_];
__device__ float g_nll   [B_];
__device__ float g_Wgp   [WGP_];     // ln_g[d]*W[d][c], padded [p][64][20]
__device__ float g_colsum[C_];       // sum_d ln_g[d]*W[d][c]
__device__ float g_bb    [C_];       // b[c] + sum_d ln_b[d]*W[d][c]

// ---------------------------------------------------------------------------
// packed f32x2 helpers
// ---------------------------------------------------------------------------
__device__ __forceinline__ unsigned long long pack2(float lo, float hi) {
    unsigned long long r;
    asm("mov.b64 %0, {%1, %2};" : "=l"(r) : "f"(lo), "f"(hi));
    return r;
}
__device__ __forceinline__ void unpack2(unsigned long long v, float& lo, float& hi) {
    asm("mov.b64 {%0, %1}, %2;" : "=f"(lo), "=f"(hi) : "l"(v));
}
__device__ __forceinline__ unsigned long long fma2(unsigned long long a,
                                                   unsigned long long b,
                                                   unsigned long long c) {
    unsigned long long d;
    asm("fma.rn.f32x2 %0, %1, %2, %3;" : "=l"(d) : "l"(a), "l"(b), "l"(c));
    return d;
}
__device__ __forceinline__ unsigned long long add2(unsigned long long a,
                                                   unsigned long long b) {
    unsigned long long d;
    asm("add.rn.f32x2 %0, %1, %2;" : "=l"(d) : "l"(a), "l"(b));
    return d;
}
__device__ __forceinline__ uint32_t smem_u32(const void* p) {
    uint32_t a;
    asm("{ .reg .u64 t; cvta.to.shared.u64 t, %1; cvt.u32.u64 %0, t; }"
        : "=r"(a) : "l"(p));
    return a;
}

// ---------------------------------------------------------------------------
// k0: one-time precompute of Wg (padded layout), colsum, bb.
// ---------------------------------------------------------------------------
__global__ __launch_bounds__(256) void k0_prep(
    const float* __restrict__ ln_g,
    const float* __restrict__ ln_b,
    const float* __restrict__ W,
    const float* __restrict__ bvec)
{
    __shared__ float pc[8][C_];
    __shared__ float pb[8][C_];
    const int tid = threadIdx.x;

    for (int idx = tid; idx < D_*C_; idx += 256) {
        int d = idx / C_, c = idx - d*C_;
        g_Wgp[(d >> 6)*SEG_ + (d & 63)*C_ + c] = ln_g[d] * W[idx];
    }
    if (tid < 160) {
        int c = tid % C_, g = tid / C_;
        float cs = 0.f, bb = 0.f;
        for (int d = g*32; d < g*32 + 32; d++) {
            float w = W[d*C_ + c];
            cs += ln_g[d] * w;
            bb += ln_b[d] * w;
        }
        pc[g][c] = cs; pb[g][c] = bb;
    }
    __syncthreads();
    if (tid < C_) {
        float cs = 0.f, bb = bvec[tid];
        #pragma unroll
        for (int g = 0; g < 8; g++) { cs += pc[g][tid]; bb += pb[g][tid]; }
        g_colsum[tid] = cs;
        g_bb[tid]     = bb;
    }
}

// ---------------------------------------------------------------------------
// k1: emb gather + LN folded into (256->20) linear + log_softmax.
// 4 threads per token (64 d each), 64 tokens/block, 256 threads, grid 512.
// Register double-buffered float4 gathers; packed f32x2 accumulation;
// conflict-free padded Wg smem (p-stride 1288 words -> bank offset 8).
// ---------------------------------------------------------------------------
__global__ __launch_bounds__(256, 3) void k1_logits(
    const int*   __restrict__ words,
    const float* __restrict__ emb)
{
    __shared__ __align__(16) float sWg[WGP_];
    __shared__ float sCol[C_];
    __shared__ float sBB[C_];

    const int tid = threadIdx.x;
    const int p   = tid & 3;        // D-segment
    const int lt  = tid >> 2;       // local token
    const int tok = blockIdx.x * 64 + lt;

    for (int i = tid; i < WGP_; i += 256) sWg[i] = g_Wgp[i];
    if (tid < C_) { sCol[tid] = g_colsum[tid]; sBB[tid] = g_bb[tid]; }
    __syncthreads();

    const int wid = __ldg(&words[tok]);
    const float4* __restrict__ xg =
        reinterpret_cast<const float4*>(emb + (size_t)wid * D_) + p * 16;

    const uint32_t wb = smem_u32(sWg) + (uint32_t)p * (SEG_ * 4);

    unsigned long long acc2[10];
    #pragma unroll
    for (int k = 0; k < 10; k++) acc2[k] = 0ull;
    float sum = 0.f, sq = 0.f;

    float4 bufA[4], bufB[4];
    #pragma unroll
    for (int q = 0; q < 4; q++) bufA[q] = __ldg(&xg[q]);

    #pragma unroll
    for (int h = 0; h < 4; h++) {
        float4* cur = (h & 1) ? bufB : bufA;
        float4* nxt = (h & 1) ? bufA : bufB;
        if (h < 3) {
            #pragma unroll
            for (int q = 0; q < 4; q++) nxt[q] = __ldg(&xg[(h+1)*4 + q]);
        }
        #pragma unroll
        for (int q = 0; q < 4; q++) {
            float xs[4] = {cur[q].x, cur[q].y, cur[q].z, cur[q].w};
            #pragma unroll
            for (int e = 0; e < 4; e++) {
                const float x = xs[e];
                const int   i = h*16 + q*4 + e;
                sum += x;
                sq   = fmaf(x, x, sq);
                const unsigned long long xx = pack2(x, x);
                const uint32_t a = wb + (uint32_t)i * 80u;   // 20 floats/row
                unsigned long long w0, w1, w2, w3, w4, w5, w6, w7, w8, w9;
                asm volatile("ld.shared.v2.b64 {%0,%1}, [%2];"
                             : "=l"(w0), "=l"(w1) : "r"(a));
                asm volatile("ld.shared.v2.b64 {%0,%1}, [%2];"
                             : "=l"(w2), "=l"(w3) : "r"(a + 16u));
                asm volatile("ld.shared.v2.b64 {%0,%1}, [%2];"
                             : "=l"(w4), "=l"(w5) : "r"(a + 32u));
                asm volatile("ld.shared.v2.b64 {%0,%1}, [%2];"
                             : "=l"(w6), "=l"(w7) : "r"(a + 48u));
                asm volatile("ld.shared.v2.b64 {%0,%1}, [%2];"
                             : "=l"(w8), "=l"(w9) : "r"(a + 64u));
                acc2[0] = fma2(xx, w0, acc2[0]);
                acc2[1] = fma2(xx, w1, acc2[1]);
                acc2[2] = fma2(xx, w2, acc2[2]);
                acc2[3] = fma2(xx, w3, acc2[3]);
                acc2[4] = fma2(xx, w4, acc2[4]);
                acc2[5] = fma2(xx, w5, acc2[5]);
                acc2[6] = fma2(xx, w6, acc2[6]);
                acc2[7] = fma2(xx, w7, acc2[7]);
                acc2[8] = fma2(xx, w8, acc2[8]);
                acc2[9] = fma2(xx, w9, acc2[9]);
            }
        }
    }

    // butterfly-reduce over the 4 D-segments (lanes xor 1, 2)
    unsigned long long ss = pack2(sum, sq);
    #pragma unroll
    for (int o = 1; o <= 2; o <<= 1) {
        ss = add2(ss, __shfl_xor_sync(0xffffffffu, ss, o));
        #pragma unroll
        for (int k = 0; k < 10; k++)
            acc2[k] = add2(acc2[k], __shfl_xor_sync(0xffffffffu, acc2[k], o));
    }
    unpack2(ss, sum, sq);

    float acc[C_];
    #pragma unroll
    for (int k = 0; k < 10; k++) unpack2(acc2[k], acc[2*k], acc[2*k+1]);

    // LayerNorm epilogue + feats + log_softmax
    const float mu   = sum * (1.0f / D_);
    const float var  = fmaxf(sq * (1.0f / D_) - mu*mu, 0.f);
    const float rstd = rsqrtf(var + 1e-5f);

    float f[C_];
    float m = -3.402823e38f;
    #pragma unroll
    for (int c = 0; c < C_; c++) {
        f[c] = rstd * (acc[c] - mu * sCol[c]) + sBB[c];
        m = fmaxf(m, f[c]);
    }
    float e[C_];
    float S = 0.f;
    #pragma unroll
    for (int c = 0; c < C_; c++) { e[c] = __expf(f[c] - m); S += e[c]; }
    const float L  = logf(S);
    const float rS = 1.0f / S;

    if (p == 0) {
        float4* lp = reinterpret_cast<float4*>(&g_logits[tok*C_]);
        float4* pp = reinterpret_cast<float4*>(&g_probs [tok*C_]);
        #pragma unroll
        for (int q = 0; q < 5; q++) {
            float4 lv, pv;
            lv.x = f[4*q+0]-m-L; lv.y = f[4*q+1]-m-L;
            lv.z = f[4*q+2]-m-L; lv.w = f[4*q+3]-m-L;
            pv.x = e[4*q+0]*rS;  pv.y = e[4*q+1]*rS;
            pv.z = e[4*q+2]*rS;  pv.w = e[4*q+3]*rS;
            lp[q] = lv;
            pp[q] = pv;
        }
    }
}

// ---------------------------------------------------------------------------
// k2: CRF forward scan (probability domain) + gold score. One block per batch.
// ---------------------------------------------------------------------------
__global__ __launch_bounds__(64) void k2_crf(
    const int*   __restrict__ seq_len,
    const int*   __restrict__ target,
    const float* __restrict__ trans,
    const float* __restrict__ startv,
    const float* __restrict__ endv)
{
    __shared__ float sP[T_*C_];   // this batch's softmax probs (40 KB)
    __shared__ float sE[C_*C_];   // exp(trans)
    __shared__ float sRes[2];     // [0]=normalizer  [1]=gold

    const int b   = blockIdx.x;
    const int tid = threadIdx.x;
    const int len = seq_len[b];

    {
        const float4* src = reinterpret_cast<const float4*>(&g_probs[b*T_*C_]);
        float4*       dst = reinterpret_cast<float4*>(sP);
        #pragma unroll 4
        for (int i = tid; i < (T_*C_)/4; i += 64) dst[i] = src[i];
    }
    for (int i = tid; i < C_*C_; i += 64) sE[i] = expf(trans[i]);
    __syncthreads();

    const int warp = tid >> 5;
    const int lane = tid & 31;

    if (warp == 0) {
        const int  j   = lane;
        const bool act = (j < C_);
        float e[C_];
        #pragma unroll
        for (int i = 0; i < C_; i++) e[i] = act ? sE[i*C_ + j] : 0.f;

        float P = act ? sP[j] * expf(startv[j]) : 0.f;
        float K = 0.f;
        {
            float mx = P;
            #pragma unroll
            for (int o = 16; o > 0; o >>= 1) mx = fmaxf(mx, __shfl_xor_sync(0xffffffffu, mx, o));
            K += logf(mx);
            P = P / mx;
        }

        for (int t = 1; t < T_; t++) {
            float pr = act ? sP[t*C_ + j] : 0.f;
            float s0 = 0.f, s1 = 0.f, s2 = 0.f, s3 = 0.f;
            #pragma unroll
            for (int i = 0; i < C_; i += 4) {
                s0 += __shfl_sync(0xffffffffu, P, i    ) * e[i    ];
                s1 += __shfl_sync(0xffffffffu, P, i + 1) * e[i + 1];
                s2 += __shfl_sync(0xffffffffu, P, i + 2) * e[i + 2];
                s3 += __shfl_sync(0xffffffffu, P, i + 3) * e[i + 3];
            }
            float Pn = pr * ((s0 + s1) + (s2 + s3));
            P = (t < len) ? Pn : P;

            if ((t & 7) == 7) {
                float mx = P;
                #pragma unroll
                for (int o = 16; o > 0; o >>= 1) mx = fmaxf(mx, __shfl_xor_sync(0xffffffffu, mx, o));
                K += logf(mx);
                P = P / mx;
            }
        }
        float v = act ? P * expf(endv[j]) : 0.f;
        #pragma unroll
        for (int o = 16; o > 0; o >>= 1) v += __shfl_xor_sync(0xffffffffu, v, o);
        if (lane == 0) sRes[0] = K + logf(v);
    } else {
        const int* tg = &target[b*T_];
        float gs = 0.f;
        for (int t = lane; t < T_; t += 32) {
            if (t < len) {
                int c = tg[t];
                gs += g_logits[(b*T_ + t)*C_ + c];
                if (t >= 1) gs += trans[tg[t-1]*C_ + c];
            }
        }
        #pragma unroll
        for (int o = 16; o > 0; o >>= 1) gs += __shfl_xor_sync(0xffffffffu, gs, o);
        if (lane == 0) {
            gs += startv[tg[0]] + endv[tg[len-1]];
            sRes[1] = gs;
        }
    }
    __syncthreads();
    if (tid == 0) g_nll[b] = sRes[0] - sRes[1];
}

// ---------------------------------------------------------------------------
// k3: mean over 64 batches -> scalar output
// ---------------------------------------------------------------------------
__global__ void k3_mean(float* __restrict__ out)
{
    int lane = threadIdx.x;
    float v = g_nll[lane] + g_nll[lane + 32];
    #pragma unroll
    for (int o = 16; o > 0; o >>= 1) v += __shfl_xor_sync(0xffffffffu, v, o);
    if (lane == 0) out[0] = v * (1.0f / B_);
}

// ---------------------------------------------------------------------------
extern "C" void kernel_launch(void* const* d_in, const int* in_sizes, int n_in,
                              void* d_out, int out_size)
{
    const int*   words   = (const int*)  d_in[0];
    const int*   seq_len = (const int*)  d_in[1];
    const int*   target  = (const int*)  d_in[2];
    const float* emb     = (const float*)d_in[3];
    const float* ln_g    = (const float*)d_in[4];
    const float* ln_b    = (const float*)d_in[5];
    const float* W       = (const float*)d_in[6];
    const float* bvec    = (const float*)d_in[7];
    const float* trans   = (const float*)d_in[8];
    const float* startv  = (const float*)d_in[9];
    const float* endv    = (const float*)d_in[10];

    k0_prep  <<<1, 256>>>(ln_g, ln_b, W, bvec);
    k1_logits<<<NTOK/64, 256>>>(words, emb);
    k2_crf   <<<B_, 64>>>(seq_len, target, trans, startv, endv);
    k3_mean  <<<1, 32>>>((float*)d_out);
}

// round 12
// speedup vs baseline: 1.3704x; 1.0982x over previous
#include <cuda_runtime.h>
#include <cuda_bf16.h>
#include <cstdint>

#define B_ 64
#define T_ 512
#define D_ 256
#define C_ 20
#define NTOK (B_*T_)

// padded per-part Wg segment: 64 d * 20 c = 1280 + 8 pad = 1288 words
#define SEG_ 1288
#define WGP_ (4*SEG_)

// Scratch (static device arrays: allocation-free)
__device__ float g_logits[NTOK*C_];
__device__ float g_probs [NTOK*C_];
__device__ float g_nll   [B_];
__device__ float g_Wgp   [WGP_];     // ln_g[d]*W[d][c], padded [p][64][20]
__device__ float g_colsum[C_];       // sum_d ln_g[d]*W[d][c]
__device__ float g_bb    [C_];       // b[c] + sum_d ln_b[d]*W[d][c]

// ---------------------------------------------------------------------------
// packed f32x2 helpers
// ---------------------------------------------------------------------------
__device__ __forceinline__ unsigned long long pack2(float lo, float hi) {
    unsigned long long r;
    asm("mov.b64 %0, {%1, %2};" : "=l"(r) : "f"(lo), "f"(hi));
    return r;
}
__device__ __forceinline__ void unpack2(unsigned long long v, float& lo, float& hi) {
    asm("mov.b64 {%0, %1}, %2;" : "=f"(lo), "=f"(hi) : "l"(v));
}
__device__ __forceinline__ unsigned long long fma2(unsigned long long a,
                                                   unsigned long long b,
                                                   unsigned long long c) {
    unsigned long long d;
    asm("fma.rn.f32x2 %0, %1, %2, %3;" : "=l"(d) : "l"(a), "l"(b), "l"(c));
    return d;
}
__device__ __forceinline__ unsigned long long add2(unsigned long long a,
                                                   unsigned long long b) {
    unsigned long long d;
    asm("add.rn.f32x2 %0, %1, %2;" : "=l"(d) : "l"(a), "l"(b));
    return d;
}
__device__ __forceinline__ uint32_t smem_u32(const void* p) {
    uint32_t a;
    asm("{ .reg .u64 t; cvta.to.shared.u64 t, %1; cvt.u32.u64 %0, t; }"
        : "=r"(a) : "l"(p));
    return a;
}

// ---------------------------------------------------------------------------
// k0: one-time precompute of Wg (padded layout), colsum, bb.
// ---------------------------------------------------------------------------
__global__ __launch_bounds__(256) void k0_prep(
    const float* __restrict__ ln_g,
    const float* __restrict__ ln_b,
    const float* __restrict__ W,
    const float* __restrict__ bvec)
{
    __shared__ float pc[8][C_];
    __shared__ float pb[8][C_];
    const int tid = threadIdx.x;

    for (int idx = tid; idx < D_*C_; idx += 256) {
        int d = idx / C_, c = idx - d*C_;
        g_Wgp[(d >> 6)*SEG_ + (d & 63)*C_ + c] = ln_g[d] * W[idx];
    }
    if (tid < 160) {
        int c = tid % C_, g = tid / C_;
        float cs = 0.f, bb = 0.f;
        for (int d = g*32; d < g*32 + 32; d++) {
            float w = W[d*C_ + c];
            cs += ln_g[d] * w;
            bb += ln_b[d] * w;
        }
        pc[g][c] = cs; pb[g][c] = bb;
    }
    __syncthreads();
    if (tid < C_) {
        float cs = 0.f, bb = bvec[tid];
        #pragma unroll
        for (int g = 0; g < 8; g++) { cs += pc[g][tid]; bb += pb[g][tid]; }
        g_colsum[tid] = cs;
        g_bb[tid]     = bb;
    }
}

// ---------------------------------------------------------------------------
// k1: emb gather + LN folded into (256->20) linear + log_softmax.
// 4 threads per token (64 d each), 64 tokens/block, 256 threads, grid 512.
// __launch_bounds__(256,2): 128 regs/thread available -> NO SPILLS (the R9
// (256,3) variant capped ptxas at 85 regs against a ~95-reg live set).
// ---------------------------------------------------------------------------
__global__ __launch_bounds__(256, 2) void k1_logits(
    const int*   __restrict__ words,
    const float* __restrict__ emb)
{
    __shared__ __align__(16) float sWg[WGP_];
    __shared__ float sCol[C_];
    __shared__ float sBB[C_];

    const int tid = threadIdx.x;
    const int p   = tid & 3;        // D-segment
    const int lt  = tid >> 2;       // local token
    const int tok = blockIdx.x * 64 + lt;

    for (int i = tid; i < WGP_; i += 256) sWg[i] = g_Wgp[i];
    if (tid < C_) { sCol[tid] = g_colsum[tid]; sBB[tid] = g_bb[tid]; }
    __syncthreads();

    const int wid = __ldg(&words[tok]);
    const float4* __restrict__ xg =
        reinterpret_cast<const float4*>(emb + (size_t)wid * D_) + p * 16;

    const uint32_t wb = smem_u32(sWg) + (uint32_t)p * (SEG_ * 4);

    unsigned long long acc2[10];
    #pragma unroll
    for (int k = 0; k < 10; k++) acc2[k] = 0ull;
    float sum = 0.f, sq = 0.f;

    float4 bufA[4], bufB[4];
    #pragma unroll
    for (int q = 0; q < 4; q++) bufA[q] = __ldg(&xg[q]);

    #pragma unroll
    for (int h = 0; h < 4; h++) {
        float4* cur = (h & 1) ? bufB : bufA;
        float4* nxt = (h & 1) ? bufA : bufB;
        if (h < 3) {
            #pragma unroll
            for (int q = 0; q < 4; q++) nxt[q] = __ldg(&xg[(h+1)*4 + q]);
        }
        #pragma unroll
        for (int q = 0; q < 4; q++) {
            float xs[4] = {cur[q].x, cur[q].y, cur[q].z, cur[q].w};
            #pragma unroll
            for (int e = 0; e < 4; e++) {
                const float x = xs[e];
                const int   i = h*16 + q*4 + e;
                sum += x;
                sq   = fmaf(x, x, sq);
                const unsigned long long xx = pack2(x, x);
                const uint32_t a = wb + (uint32_t)i * 80u;   // 20 floats/row
                unsigned long long w0, w1, w2, w3, w4, w5, w6, w7, w8, w9;
                asm volatile("ld.shared.v2.b64 {%0,%1}, [%2];"
                             : "=l"(w0), "=l"(w1) : "r"(a));
                asm volatile("ld.shared.v2.b64 {%0,%1}, [%2];"
                             : "=l"(w2), "=l"(w3) : "r"(a + 16u));
                asm volatile("ld.shared.v2.b64 {%0,%1}, [%2];"
                             : "=l"(w4), "=l"(w5) : "r"(a + 32u));
                asm volatile("ld.shared.v2.b64 {%0,%1}, [%2];"
                             : "=l"(w6), "=l"(w7) : "r"(a + 48u));
                asm volatile("ld.shared.v2.b64 {%0,%1}, [%2];"
                             : "=l"(w8), "=l"(w9) : "r"(a + 64u));
                acc2[0] = fma2(xx, w0, acc2[0]);
                acc2[1] = fma2(xx, w1, acc2[1]);
                acc2[2] = fma2(xx, w2, acc2[2]);
                acc2[3] = fma2(xx, w3, acc2[3]);
                acc2[4] = fma2(xx, w4, acc2[4]);
                acc2[5] = fma2(xx, w5, acc2[5]);
                acc2[6] = fma2(xx, w6, acc2[6]);
                acc2[7] = fma2(xx, w7, acc2[7]);
                acc2[8] = fma2(xx, w8, acc2[8]);
                acc2[9] = fma2(xx, w9, acc2[9]);
            }
        }
    }

    // butterfly-reduce over the 4 D-segments (lanes xor 1, 2)
    unsigned long long ss = pack2(sum, sq);
    #pragma unroll
    for (int o = 1; o <= 2; o <<= 1) {
        ss = add2(ss, __shfl_xor_sync(0xffffffffu, ss, o));
        #pragma unroll
        for (int k = 0; k < 10; k++)
            acc2[k] = add2(acc2[k], __shfl_xor_sync(0xffffffffu, acc2[k], o));
    }
    unpack2(ss, sum, sq);

    float acc[C_];
    #pragma unroll
    for (int k = 0; k < 10; k++) unpack2(acc2[k], acc[2*k], acc[2*k+1]);

    // LayerNorm epilogue + feats + log_softmax
    const float mu   = sum * (1.0f / D_);
    const float var  = fmaxf(sq * (1.0f / D_) - mu*mu, 0.f);
    const float rstd = rsqrtf(var + 1e-5f);

    float f[C_];
    float m = -3.402823e38f;
    #pragma unroll
    for (int c = 0; c < C_; c++) {
        f[c] = rstd * (acc[c] - mu * sCol[c]) + sBB[c];
        m = fmaxf(m, f[c]);
    }
    float e[C_];
    float S = 0.f;
    #pragma unroll
    for (int c = 0; c < C_; c++) { e[c] = __expf(f[c] - m); S += e[c]; }
    const float L  = __logf(S);
    const float rS = 1.0f / S;

    if (p == 0) {
        float4* lp = reinterpret_cast<float4*>(&g_logits[tok*C_]);
        float4* pp = reinterpret_cast<float4*>(&g_probs [tok*C_]);
        #pragma unroll
        for (int q = 0; q < 5; q++) {
            float4 lv, pv;
            lv.x = f[4*q+0]-m-L; lv.y = f[4*q+1]-m-L;
            lv.z = f[4*q+2]-m-L; lv.w = f[4*q+3]-m-L;
            pv.x = e[4*q+0]*rS;  pv.y = e[4*q+1]*rS;
            pv.z = e[4*q+2]*rS;  pv.w = e[4*q+3]*rS;
            lp[q] = lv;
            pp[q] = pv;
        }
    }
}

// ---------------------------------------------------------------------------
// k2: CRF forward scan (probability domain) + gold score. One block per batch.
//   warp 0: sequential scan with fast-math renorm (MUFU log/div).
//   warp 1: gold path score (parallel over t).
// ---------------------------------------------------------------------------
__global__ __launch_bounds__(64) void k2_crf(
    const int*   __restrict__ seq_len,
    const int*   __restrict__ target,
    const float* __restrict__ trans,
    const float* __restrict__ startv,
    const float* __restrict__ endv)
{
    __shared__ float sP[T_*C_];   // this batch's softmax probs (40 KB)
    __shared__ float sE[C_*C_];   // exp(trans)
    __shared__ float sRes[2];     // [0]=normalizer  [1]=gold

    const int b   = blockIdx.x;
    const int tid = threadIdx.x;
    const int len = seq_len[b];

    {
        const float4* src = reinterpret_cast<const float4*>(&g_probs[b*T_*C_]);
        float4*       dst = reinterpret_cast<float4*>(sP);
        #pragma unroll 4
        for (int i = tid; i < (T_*C_)/4; i += 64) dst[i] = src[i];
    }
    for (int i = tid; i < C_*C_; i += 64) sE[i] = __expf(trans[i]);
    __syncthreads();

    const int warp = tid >> 5;
    const int lane = tid & 31;

    if (warp == 0) {
        const int  j   = lane;
        const bool act = (j < C_);
        float e[C_];
        #pragma unroll
        for (int i = 0; i < C_; i++) e[i] = act ? sE[i*C_ + j] : 0.f;

        float P = act ? sP[j] * __expf(startv[j]) : 0.f;
        float K = 0.f;
        {
            float mx = P;
            #pragma unroll
            for (int o = 16; o > 0; o >>= 1) mx = fmaxf(mx, __shfl_xor_sync(0xffffffffu, mx, o));
            K += __logf(mx);
            float rmx = __fdividef(1.0f, mx);
            P = P * rmx;
        }

        for (int t = 1; t < T_; t++) {
            float pr = act ? sP[t*C_ + j] : 0.f;
            float s0 = 0.f, s1 = 0.f, s2 = 0.f, s3 = 0.f;
            #pragma unroll
            for (int i = 0; i < C_; i += 4) {
                s0 += __shfl_sync(0xffffffffu, P, i    ) * e[i    ];
                s1 += __shfl_sync(0xffffffffu, P, i + 1) * e[i + 1];
                s2 += __shfl_sync(0xffffffffu, P, i + 2) * e[i + 2];
                s3 += __shfl_sync(0xffffffffu, P, i + 3) * e[i + 3];
            }
            float Pn = pr * ((s0 + s1) + (s2 + s3));
            P = (t < len) ? Pn : P;

            if ((t & 7) == 7) {
                float mx = P;
                #pragma unroll
                for (int o = 16; o > 0; o >>= 1) mx = fmaxf(mx, __shfl_xor_sync(0xffffffffu, mx, o));
                K += __logf(mx);
                float rmx = __fdividef(1.0f, mx);
                P = P * rmx;
            }
        }
        float v = act ? P * __expf(endv[j]) : 0.f;
        #pragma unroll
        for (int o = 16; o > 0; o >>= 1) v += __shfl_xor_sync(0xffffffffu, v, o);
        if (lane == 0) sRes[0] = K + __logf(v);
    } else {
        const int* tg = &target[b*T_];
        float gs = 0.f;
        for (int t = lane; t < T_; t += 32) {
            if (t < len) {
                int c = tg[t];
                gs += g_logits[(b*T_ + t)*C_ + c];
                if (t >= 1) gs += trans[tg[t-1]*C_ + c];
            }
        }
        #pragma unroll
        for (int o = 16; o > 0; o >>= 1) gs += __shfl_xor_sync(0xffffffffu, gs, o);
        if (lane == 0) {
            gs += startv[tg[0]] + endv[tg[len-1]];
            sRes[1] = gs;
        }
    }
    __syncthreads();
    if (tid == 0) g_nll[b] = sRes[0] - sRes[1];
}

// ---------------------------------------------------------------------------
// k3: mean over 64 batches -> scalar output
// ---------------------------------------------------------------------------
__global__ void k3_mean(float* __restrict__ out)
{
    int lane = threadIdx.x;
    float v = g_nll[lane] + g_nll[lane + 32];
    #pragma unroll
    for (int o = 16; o > 0; o >>= 1) v += __shfl_xor_sync(0xffffffffu, v, o);
    if (lane == 0) out[0] = v * (1.0f / B_);
}

// ---------------------------------------------------------------------------
extern "C" void kernel_launch(void* const* d_in, const int* in_sizes, int n_in,
                              void* d_out, int out_size)
{
    const int*   words   = (const int*)  d_in[0];
    const int*   seq_len = (const int*)  d_in[1];
    const int*   target  = (const int*)  d_in[2];
    const float* emb     = (const float*)d_in[3];
    const float* ln_g    = (const float*)d_in[4];
    const float* ln_b    = (const float*)d_in[5];
    const float* W       = (const float*)d_in[6];
    const float* bvec    = (const float*)d_in[7];
    const float* trans   = (const float*)d_in[8];
    const float* startv  = (const float*)d_in[9];
    const float* endv    = (const float*)d_in[10];

    k0_prep  <<<1, 256>>>(ln_g, ln_b, W, bvec);
    k1_logits<<<NTOK/64, 256>>>(words, emb);
    k2_crf   <<<B_, 64>>>(seq_len, target, trans, startv, endv);
    k3_mean  <<<1, 32>>>((float*)d_out);
}